// round 16
// baseline (speedup 1.0000x reference)
#include <cuda_runtime.h>
#include <cuda_bf16.h>
#include <cuda_fp8.h>
#include <cstdint>

// ---------------------------------------------------------------------------
// GCNEncoder, collapsed form.
//   out = (1/n) (sum_j c[j] h1[j]) W2 + b2
//   c[j]  = dis[j] * ( sum_{edges src=j} dis[dst] + dis[j] )
//   h1[i] = relu( dis[i]*(sum_{j in N_in(i)} h'[j] + h'[i]) + b1 )
//   h'[j] = (x W1)[j] * dis[j]   -- stored e4m3; gather 256B/row (L2-res).
//
// R15 finding: occupancy is NOT the GEMM limiter (occ +55%, dur flat).
// Hypothesis now: barrier cadence (sync every BK=16 -> too little work per
// barrier). This round: 2 k-tiles per sync (8 barriers, 32 mma + 12 ldsm
// each), 5-slot cp.async ring, dynamic smem, same 128x128 geometry.
// ---------------------------------------------------------------------------

#define NMAX 100000
#define EMAX 3200000
#define DIM  256
#define AGG_BLOCKS ((NMAX + 7) / 8)

__device__ int   g_deg[NMAX];
__device__ float g_dis[NMAX];
__device__ float g_coef[NMAX];
__device__ int   g_rowptr[NMAX + 1];
__device__ int   g_cursor[NMAX];
__device__ int   g_col[EMAX];
__device__ __align__(16) __nv_bfloat16 g_xb[(size_t)NMAX * DIM];  // x bf16 [M,K]
__device__ __align__(16) __nv_bfloat16 g_wb[DIM * DIM];           // W1 bf16 [K,N]
__device__ __align__(16) uint8_t g_h8[(size_t)NMAX * DIM];        // h' e4m3
__device__ float g_part[(size_t)AGG_BLOCKS * DIM];
__device__ float g_part2[256 * DIM];
__device__ int   g_bsum[256];

// ------------------------------- helpers -----------------------------------

__device__ __forceinline__ uint32_t smem_u32(const void* p) {
    return (uint32_t)__cvta_generic_to_shared(p);
}

__device__ __forceinline__ uint2 pack4(float4 v) {
    __nv_bfloat162 a = __floats2bfloat162_rn(v.x, v.y);
    __nv_bfloat162 b = __floats2bfloat162_rn(v.z, v.w);
    return make_uint2(*(uint32_t*)&a, *(uint32_t*)&b);
}

__device__ __forceinline__ void cp_async16(uint32_t smem, const void* g, int src_bytes) {
    asm volatile("cp.async.cg.shared.global [%0], [%1], 16, %2;"
                 :: "r"(smem), "l"(g), "r"(src_bytes) : "memory");
}
__device__ __forceinline__ void cp_commit() {
    asm volatile("cp.async.commit_group;" ::: "memory");
}
template <int N>
__device__ __forceinline__ void cp_wait() {
    asm volatile("cp.async.wait_group %0;" :: "n"(N) : "memory");
}

__device__ __forceinline__ void ldsm4(uint32_t* r, uint32_t a) {
    asm volatile("ldmatrix.sync.aligned.m8n8.x4.shared.b16 {%0,%1,%2,%3}, [%4];"
                 : "=r"(r[0]), "=r"(r[1]), "=r"(r[2]), "=r"(r[3]) : "r"(a));
}
__device__ __forceinline__ void ldsm4t(uint32_t* r, uint32_t a) {
    asm volatile("ldmatrix.sync.aligned.m8n8.x4.trans.shared.b16 {%0,%1,%2,%3}, [%4];"
                 : "=r"(r[0]), "=r"(r[1]), "=r"(r[2]), "=r"(r[3]) : "r"(a));
}
__device__ __forceinline__ void mma_bf16(float* d, const uint32_t* a, uint32_t b0, uint32_t b1) {
    asm volatile(
        "mma.sync.aligned.m16n8k16.row.col.f32.bf16.bf16.f32 "
        "{%0,%1,%2,%3}, {%4,%5,%6,%7}, {%8,%9}, {%0,%1,%2,%3};"
        : "+f"(d[0]), "+f"(d[1]), "+f"(d[2]), "+f"(d[3])
        : "r"(a[0]), "r"(a[1]), "r"(a[2]), "r"(a[3]), "r"(b0), "r"(b1));
}

// pack two f32 into e4m3x2 (result .b16; first PTX src packs the high byte)
__device__ __forceinline__ uint16_t f2e4m3x2(float a, float b) {
    uint16_t r;
    asm("cvt.rn.satfinite.e4m3x2.f32 %0, %1, %2;" : "=h"(r) : "f"(b), "f"(a));
    return r;
}

// ---------------------- degree count + bf16 conversion ---------------------

__global__ void k_count_convert(const int* __restrict__ dst, int e,
                                const float* __restrict__ x,
                                const float* __restrict__ W1, int n) {
    int i = blockIdx.x * blockDim.x + threadIdx.x;
    int nth = gridDim.x * blockDim.x;
    if (i < e) atomicAdd(&g_deg[dst[i]], 1);

    const float4* __restrict__ x4 = (const float4*)x;
    uint2* __restrict__ xb2 = (uint2*)g_xb;
    int total4 = n * (DIM / 4);
    for (int idx = i; idx < total4; idx += nth)
        xb2[idx] = pack4(x4[idx]);

    const float4* __restrict__ w4 = (const float4*)W1;
    uint2* __restrict__ wb2 = (uint2*)g_wb;
    for (int idx = i; idx < DIM * DIM / 4; idx += nth)
        wb2[idx] = pack4(w4[idx]);
}

// block TOTALS over 1024-entry chunks; also computes dis = rsqrt(deg+1)
__global__ void k_block_sums(int n) {
    __shared__ int sh[256];
    int base = blockIdx.x * 1024;
    int s = 0;
#pragma unroll
    for (int q = 0; q < 4; q++) {
        int i = base + q * 256 + threadIdx.x;
        if (i < n) {
            int d = g_deg[i];
            s += d;
            g_dis[i] = rsqrtf((float)d + 1.0f);
        }
    }
    sh[threadIdx.x] = s;
    __syncthreads();
    for (int off = 128; off > 0; off >>= 1) {
        if (threadIdx.x < off) sh[threadIdx.x] += sh[threadIdx.x + off];
        __syncthreads();
    }
    if (threadIdx.x == 0) g_bsum[blockIdx.x] = sh[0];
}

// per-block scan; each block derives its global offset from preceding totals
__global__ void k_scan_blocks(int n, int e_total) {
    __shared__ int sh[1024];
    __shared__ int wsum[32];

    int pre = (threadIdx.x < blockIdx.x) ? g_bsum[threadIdx.x] : 0;
#pragma unroll
    for (int off = 16; off > 0; off >>= 1)
        pre += __shfl_down_sync(0xffffffffu, pre, off);
    if ((threadIdx.x & 31) == 0) wsum[threadIdx.x >> 5] = pre;
    __syncthreads();
    if (threadIdx.x == 0) {
        int s = 0;
#pragma unroll
        for (int w = 0; w < 32; w++) s += wsum[w];
        wsum[0] = s;
    }
    __syncthreads();
    int blockoff = wsum[0];

    int i = blockIdx.x * 1024 + threadIdx.x;
    int v = (i < n) ? g_deg[i] : 0;
    sh[threadIdx.x] = v;
    __syncthreads();
    for (int off = 1; off < 1024; off <<= 1) {
        int t = 0;
        if ((int)threadIdx.x >= off) t = sh[threadIdx.x - off];
        __syncthreads();
        sh[threadIdx.x] += t;
        __syncthreads();
    }
    int excl = sh[threadIdx.x] - v;
    if (i < n) {
        int r = excl + blockoff;
        g_rowptr[i] = r;
        g_cursor[i] = r;
    }
    if (i == 0) g_rowptr[n] = e_total;
}

// ------ bf16 GEMM 128x128, 2 k-tiles per barrier, 5-slot cp.async ring ------
// 8 warps (4x2), warp tile 32x64. grid (2, Mtiles) for L2 A reuse.

#define AS 24     // A smem row stride (bf16 elems)
#define BSTR 136  // B smem row stride (bf16 elems)
#define STAGES 5
#define A_TILE (128 * AS)
#define B_TILE (16 * BSTR)
#define GEMM_DSM (STAGES * (A_TILE + B_TILE) * 2)

__global__ __launch_bounds__(256, 2)
void k_gemm_scatter(int M, const int* __restrict__ esrc,
                    const int* __restrict__ edst, int E) {
    extern __shared__ char dsm[];
    __nv_bfloat16* Ah = (__nv_bfloat16*)dsm;
    __nv_bfloat16* Bh = Ah + STAGES * A_TILE;

    int tid = threadIdx.x;
    int bm = blockIdx.y * 128;   // M-tile
    int bn = blockIdx.x * 128;   // N-tile (grid.x = 2; pair co-resident)
    int wid = tid >> 5;
    int lane = tid & 31;
    int wm = (wid & 3) * 32;
    int wn = (wid >> 2) * 64;
    int qr = lane >> 2, qc = lane & 3;

    // cp.async mapping: A 128 rows x 2 chunks(16B); B 16 rows x 16 chunks
    int arow = tid >> 1, ach = (tid & 1) * 8;
    int brow = tid >> 4, bch = (tid & 15) * 8;
    uint32_t adA = smem_u32(&Ah[arow * AS + ach]);
    uint32_t adB = smem_u32(&Bh[brow * BSTR + bch]);
    int ar = bm + arow;
    int aValid = (ar < M) ? 16 : 0;
    if (ar >= M) ar = M - 1;
    const __nv_bfloat16* aSrc = g_xb + (size_t)ar * 256 + ach;
    const __nv_bfloat16* bSrc = g_wb + (size_t)brow * 256 + bn + bch;

    int la = lane & 15, lb = lane >> 4;
    uint32_t adAh = smem_u32(Ah) + (uint32_t)(((wm + la) * AS + lb * 8) * 2);
    uint32_t adBh = smem_u32(Bh) + (uint32_t)((la * BSTR + wn + lb * 8) * 2);

    float d[2][8][4];
#pragma unroll
    for (int i = 0; i < 2; i++)
#pragma unroll
        for (int j = 0; j < 8; j++)
#pragma unroll
            for (int q = 0; q < 4; q++) d[i][j][q] = 0.0f;

    // prologue: tiles 0..2 into slots 0..2 (one commit group per tile)
#pragma unroll
    for (int s = 0; s < 3; s++) {
        cp_async16(adA + s * A_TILE * 2, aSrc + s * 16, aValid);
        cp_async16(adB + s * B_TILE * 2, bSrc + (size_t)(s * 16) * 256, 16);
        cp_commit();
    }

    // 8 iterations, 2 k-tiles each; slots mod 5 guarantee no overwrite of
    // the two tiles being computed (in-flight tiles t+2..t+4 vs t,t+1).
    for (int t = 0; t < 16; t += 2) {
        cp_wait<1>();          // tiles 0..t+1 complete
        __syncthreads();

        // issue tiles t+3, t+4
#pragma unroll
        for (int u = 3; u <= 4; u++) {
            int nt = t + u;
            if (nt < 16) {
                int slot = nt % STAGES;
                cp_async16(adA + slot * A_TILE * 2, aSrc + nt * 16, aValid);
                cp_async16(adB + slot * B_TILE * 2, bSrc + (size_t)(nt * 16) * 256, 16);
            }
            cp_commit();
        }

        // compute tiles t, t+1 (32 mma, 12 ldsm per warp before next barrier)
#pragma unroll
        for (int u = 0; u < 2; u++) {
            int slot = (t + u) % STAGES;
            uint32_t aoff = (uint32_t)(slot * A_TILE * 2);
            uint32_t boff = (uint32_t)(slot * B_TILE * 2);
            uint32_t ah0[4], ah1[4];
            ldsm4(ah0, adAh + aoff);
            ldsm4(ah1, adAh + aoff + 16 * AS * 2);
#pragma unroll
            for (int q = 0; q < 4; q++) {
                uint32_t bh[4];
                ldsm4t(bh, adBh + boff + q * 32);
                mma_bf16(d[0][2 * q],     ah0, bh[0], bh[1]);
                mma_bf16(d[1][2 * q],     ah1, bh[0], bh[1]);
                mma_bf16(d[0][2 * q + 1], ah0, bh[2], bh[3]);
                mma_bf16(d[1][2 * q + 1], ah1, bh[2], bh[3]);
            }
        }
    }

    // epilogue: * dis[row], convert to e4m3 pairs, 2B stores
#pragma unroll
    for (int ma = 0; ma < 2; ma++) {
        int r0 = bm + wm + 16 * ma + qr;
        int r1 = r0 + 8;
        float w0 = (r0 < M) ? g_dis[r0] : 0.0f;
        float w1 = (r1 < M) ? g_dis[r1] : 0.0f;
#pragma unroll
        for (int na = 0; na < 8; na++) {
            int c = bn + wn + 8 * na + 2 * qc;
            if (r0 < M) {
                uint16_t p = f2e4m3x2(d[ma][na][0] * w0, d[ma][na][1] * w0);
                *(uint16_t*)(&g_h8[(size_t)r0 * 256 + c]) = p;
            }
            if (r1 < M) {
                uint16_t p = f2e4m3x2(d[ma][na][2] * w1, d[ma][na][3] * w1);
                *(uint16_t*)(&g_h8[(size_t)r1 * 256 + c]) = p;
            }
        }
    }

    // ---- tail: scatter this block's slice of edges into CSR (+ coef) ----
    {
        int nblocks = gridDim.x * gridDim.y;
        int bid = blockIdx.y * gridDim.x + blockIdx.x;
        int per = (E + nblocks - 1) / nblocks;
        int e0 = bid * per;
        int e1 = min(e0 + per, E);
        for (int i = e0 + tid; i < e1; i += 256) {
            int s = esrc[i];
            int dd = edst[i];
            int p = atomicAdd(&g_cursor[dd], 1);
            g_col[p] = s;
            atomicAdd(&g_coef[s], g_dis[dd]);
        }
    }
}

// -------------------- fused aggregation + weighted reduce -------------------

__device__ __forceinline__ __half2 e8_to_h2(uint16_t w) {
    uint32_t r;
    asm("cvt.rn.f16x2.e4m3x2 %0, %1;" : "=r"(r) : "h"(w));
    return *(__half2*)&r;
}

__global__ __launch_bounds__(256)
void k_agg_fused(const float* __restrict__ bias, int n) {
    __shared__ float sh[8][256];

    int lane = threadIdx.x & 31;
    int w = threadIdx.x >> 5;
    int i = blockIdx.x * 8 + w;

    const uint2* __restrict__ hp = (const uint2*)g_h8;
    float res[8];
#pragma unroll
    for (int q = 0; q < 8; q++) res[q] = 0.0f;

    if (i < n) {
        int s = g_rowptr[i];
        int t = g_rowptr[i + 1];
        float di = g_dis[i];
        float ci = di * (g_coef[i] + di);

        __half2 acc[4];
        {
            uint2 sv = hp[(size_t)i * 32 + lane];
            acc[0] = e8_to_h2((uint16_t)(sv.x & 0xffffu));
            acc[1] = e8_to_h2((uint16_t)(sv.x >> 16));
            acc[2] = e8_to_h2((uint16_t)(sv.y & 0xffffu));
            acc[3] = e8_to_h2((uint16_t)(sv.y >> 16));
        }

        for (int base = s; base < t; base += 32) {
            int m = min(32, t - base);
            int jv = (base + lane < t) ? g_col[base + lane] : 0;
#pragma unroll 8
            for (int k = 0; k < m; k++) {
                int j = __shfl_sync(0xffffffffu, jv, k);
                uint2 v = hp[(size_t)j * 32 + lane];
                acc[0] = __hadd2(acc[0], e8_to_h2((uint16_t)(v.x & 0xffffu)));
                acc[1] = __hadd2(acc[1], e8_to_h2((uint16_t)(v.x >> 16)));
                acc[2] = __hadd2(acc[2], e8_to_h2((uint16_t)(v.y & 0xffffu)));
                acc[3] = __hadd2(acc[3], e8_to_h2((uint16_t)(v.y >> 16)));
            }
        }

        float4 b0 = *(const float4*)(bias + lane * 8);
        float4 b1 = *(const float4*)(bias + lane * 8 + 4);
        float2 f0 = __half22float2(acc[0]);
        float2 f1 = __half22float2(acc[1]);
        float2 f2 = __half22float2(acc[2]);
        float2 f3 = __half22float2(acc[3]);
        res[0] = fmaxf(f0.x * di + b0.x, 0.f) * ci;
        res[1] = fmaxf(f0.y * di + b0.y, 0.f) * ci;
        res[2] = fmaxf(f1.x * di + b0.z, 0.f) * ci;
        res[3] = fmaxf(f1.y * di + b0.w, 0.f) * ci;
        res[4] = fmaxf(f2.x * di + b1.x, 0.f) * ci;
        res[5] = fmaxf(f2.y * di + b1.y, 0.f) * ci;
        res[6] = fmaxf(f3.x * di + b1.z, 0.f) * ci;
        res[7] = fmaxf(f3.y * di + b1.w, 0.f) * ci;
    }

#pragma unroll
    for (int q = 0; q < 8; q++) sh[w][lane * 8 + q] = res[q];
    __syncthreads();

    int c = threadIdx.x;
    float ssum = 0.0f;
#pragma unroll
    for (int q = 0; q < 8; q++) ssum += sh[q][c];
    g_part[(size_t)blockIdx.x * 256 + c] = ssum;
}

// ------------------------------- reductions --------------------------------

__global__ void k_reduce_stage1(int nb) {
    int c = threadIdx.x;
    int rows_per = (nb + 255) / 256;
    int r0 = blockIdx.x * rows_per;
    int r1 = min(r0 + rows_per, nb);
    float s = 0.0f;
    for (int r = r0; r < r1; r++) s += g_part[(size_t)r * 256 + c];
    g_part2[blockIdx.x * 256 + c] = s;
}

__global__ void k_final(const float* __restrict__ W2, const float* __restrict__ b2,
                        float* __restrict__ out, int n) {
    __shared__ float z[256];
    int c = threadIdx.x;
    float s = 0.0f;
    for (int b = 0; b < 256; b++) s += g_part2[b * 256 + c];
    z[c] = s / (float)n;
    __syncthreads();

    float o = b2[c];
#pragma unroll 8
    for (int k = 0; k < 256; k++) o += z[k] * W2[k * 256 + c];
    out[c] = o;
}

// -------------------------------- launch -----------------------------------

extern "C" void kernel_launch(void* const* d_in, const int* in_sizes, int n_in,
                              void* d_out, int out_size) {
    const float* x  = (const float*)d_in[0];
    const float* W1 = (const float*)d_in[1];
    const float* b1 = (const float*)d_in[2];
    const float* W2 = (const float*)d_in[3];
    const float* b2 = (const float*)d_in[4];
    const int*   ei = (const int*)d_in[5];

    int n = in_sizes[0] / DIM;
    int e = in_sizes[5] / 2;
    const int* src = ei;
    const int* dst = ei + e;
    float* out = (float*)d_out;

    int nb1024 = (n + 1023) / 1024;
    int agg_blocks = (n + 7) / 8;

    // zero deg/coef via memset nodes (not kernel launches)
    void* p_deg;
    void* p_coef;
    cudaGetSymbolAddress(&p_deg, g_deg);
    cudaGetSymbolAddress(&p_coef, g_coef);
    cudaMemsetAsync(p_deg, 0, (size_t)n * sizeof(int));
    cudaMemsetAsync(p_coef, 0, (size_t)n * sizeof(float));

    // --- degree count + bf16 conversion of x, W1 ---
    k_count_convert<<<(e + 255) / 256, 256>>>(dst, e, x, W1, n);
    k_block_sums<<<nb1024, 256>>>(n);          // dis + block totals
    k_scan_blocks<<<nb1024, 1024>>>(n, e);     // rowptr + cursor

    // --- layer-1 GEMM (bf16, 2 tiles/barrier, 5-slot ring) + scatter ---
    cudaFuncSetAttribute(k_gemm_scatter,
                         cudaFuncAttributeMaxDynamicSharedMemorySize, GEMM_DSM);
    dim3 gemm_grid(2, (n + 127) / 128);
    k_gemm_scatter<<<gemm_grid, 256, GEMM_DSM>>>(n, src, dst, e);

    // --- fused aggregate + relu + weighted reduce (layer 2 collapsed) ---
    k_agg_fused<<<agg_blocks, 256>>>(b1, n);

    // --- reduce partials, matvec with W2, bias, mean ---
    k_reduce_stage1<<<256, 256>>>(agg_blocks);
    k_final<<<1, 256>>>(W2, b2, out, n);
}

// round 17
// speedup vs baseline: 1.0130x; 1.0130x over previous
#include <cuda_runtime.h>
#include <cuda_bf16.h>
#include <cuda_fp8.h>
#include <cstdint>

// ---------------------------------------------------------------------------
// GCNEncoder, collapsed form.
//   out = (1/n) (sum_j c[j] h1[j]) W2 + b2
//   c[j]  = dis[j] * ( sum_{edges src=j} dis[dst] + dis[j] )
//   h1[i] = relu( dis[i]*(sum_{j in N_in(i)} h'[j] + h'[i]) + b1 )
//   h'[j] = (x W1)[j] * dis[j]   -- stored e4m3; gather 256B/row (L2-res).
//
// R16 conclusion: mma.sync GEMM is at the legacy-HMMA pipe ceiling (~17%
// tensor of tcgen05 peak, invariant under DRAM/MLP/occupancy/barrier
// changes); tcgen05 unavailable (ptxas sm_103). GEMM frozen at R13 config.
// This round: fused single-kernel CSR scan (publish+spin cross-block
// prefix), agg col-prefetch, fewer launches; agg becomes launch #3 so the
// next ncu window profiles it.
// ---------------------------------------------------------------------------

#define NMAX 100000
#define EMAX 3200000
#define DIM  256
#define AGG_BLOCKS ((NMAX + 7) / 8)

__device__ int   g_deg[NMAX];
__device__ float g_dis[NMAX];
__device__ float g_coef[NMAX];
__device__ int   g_rowptr[NMAX + 1];
__device__ int   g_cursor[NMAX];
__device__ int   g_col[EMAX];
__device__ __align__(16) __nv_bfloat16 g_xb[(size_t)NMAX * DIM];  // x bf16 [M,K]
__device__ __align__(16) __nv_bfloat16 g_wb[DIM * DIM];           // W1 bf16 [K,N]
__device__ __align__(16) uint8_t g_h8[(size_t)NMAX * DIM];        // h' e4m3
__device__ float g_part[(size_t)AGG_BLOCKS * DIM];
__device__ float g_part2[256 * DIM];
__device__ unsigned long long g_bpub[256];   // (flag<<63 | block total)

// ------------------------------- helpers -----------------------------------

__device__ __forceinline__ uint32_t smem_u32(const void* p) {
    return (uint32_t)__cvta_generic_to_shared(p);
}

__device__ __forceinline__ uint2 pack4(float4 v) {
    __nv_bfloat162 a = __floats2bfloat162_rn(v.x, v.y);
    __nv_bfloat162 b = __floats2bfloat162_rn(v.z, v.w);
    return make_uint2(*(uint32_t*)&a, *(uint32_t*)&b);
}

__device__ __forceinline__ void cp_async16(uint32_t smem, const void* g, int src_bytes) {
    asm volatile("cp.async.cg.shared.global [%0], [%1], 16, %2;"
                 :: "r"(smem), "l"(g), "r"(src_bytes) : "memory");
}
__device__ __forceinline__ void cp_commit() {
    asm volatile("cp.async.commit_group;" ::: "memory");
}
template <int N>
__device__ __forceinline__ void cp_wait() {
    asm volatile("cp.async.wait_group %0;" :: "n"(N) : "memory");
}

__device__ __forceinline__ void ldsm4(uint32_t* r, uint32_t a) {
    asm volatile("ldmatrix.sync.aligned.m8n8.x4.shared.b16 {%0,%1,%2,%3}, [%4];"
                 : "=r"(r[0]), "=r"(r[1]), "=r"(r[2]), "=r"(r[3]) : "r"(a));
}
__device__ __forceinline__ void ldsm4t(uint32_t* r, uint32_t a) {
    asm volatile("ldmatrix.sync.aligned.m8n8.x4.trans.shared.b16 {%0,%1,%2,%3}, [%4];"
                 : "=r"(r[0]), "=r"(r[1]), "=r"(r[2]), "=r"(r[3]) : "r"(a));
}
__device__ __forceinline__ void mma_bf16(float* d, const uint32_t* a, uint32_t b0, uint32_t b1) {
    asm volatile(
        "mma.sync.aligned.m16n8k16.row.col.f32.bf16.bf16.f32 "
        "{%0,%1,%2,%3}, {%4,%5,%6,%7}, {%8,%9}, {%0,%1,%2,%3};"
        : "+f"(d[0]), "+f"(d[1]), "+f"(d[2]), "+f"(d[3])
        : "r"(a[0]), "r"(a[1]), "r"(a[2]), "r"(a[3]), "r"(b0), "r"(b1));
}

// pack two f32 into e4m3x2 (result .b16; first PTX src packs the high byte)
__device__ __forceinline__ uint16_t f2e4m3x2(float a, float b) {
    uint16_t r;
    asm("cvt.rn.satfinite.e4m3x2.f32 %0, %1, %2;" : "=h"(r) : "f"(b), "f"(a));
    return r;
}

// ---------------------- degree count + bf16 conversion ---------------------

__global__ void k_count_convert(const int* __restrict__ dst, int e,
                                const float* __restrict__ x,
                                const float* __restrict__ W1, int n) {
    int i = blockIdx.x * blockDim.x + threadIdx.x;
    int nth = gridDim.x * blockDim.x;
    if (i < e) atomicAdd(&g_deg[dst[i]], 1);

    const float4* __restrict__ x4 = (const float4*)x;
    uint2* __restrict__ xb2 = (uint2*)g_xb;
    int total4 = n * (DIM / 4);
    for (int idx = i; idx < total4; idx += nth)
        xb2[idx] = pack4(x4[idx]);

    const float4* __restrict__ w4 = (const float4*)W1;
    uint2* __restrict__ wb2 = (uint2*)g_wb;
    for (int idx = i; idx < DIM * DIM / 4; idx += nth)
        wb2[idx] = pack4(w4[idx]);
}

// ------------- fused scan: dis + rowptr + cursor in ONE kernel -------------
// 98 blocks x 1024 threads (all wave-1 resident on 148 SMs -> spin is safe).
// Each block: intra-block inclusive scan of deg, publish its total with a
// flag bit in one 64-bit word, spin-read predecessors' totals for the offset.

__global__ void k_scan_fused(int n, int e_total) {
    __shared__ int sh[1024];
    __shared__ int wsum[32];
    __shared__ int s_off;

    int tid = threadIdx.x;
    int bid = blockIdx.x;
    int i = bid * 1024 + tid;

    int v = 0;
    if (i < n) {
        v = g_deg[i];
        g_dis[i] = rsqrtf((float)v + 1.0f);
    }
    sh[tid] = v;
    __syncthreads();
    for (int off = 1; off < 1024; off <<= 1) {
        int t = 0;
        if (tid >= off) t = sh[tid - off];
        __syncthreads();
        sh[tid] += t;
        __syncthreads();
    }

    // publish this block's total (sh[1023]) with flag bit
    if (tid == 0) {
        unsigned long long pub = (1ull << 63) | (unsigned int)sh[1023];
        atomicExch(&g_bpub[bid], pub);
    }

    // block offset = sum of predecessor totals (spin until published)
    int pre = 0;
    if (tid < bid) {
        unsigned long long pv;
        do {
            pv = ((volatile unsigned long long*)g_bpub)[tid];
        } while (!(pv >> 63));
        pre = (int)(pv & 0xffffffffull);
    }
#pragma unroll
    for (int off = 16; off > 0; off >>= 1)
        pre += __shfl_down_sync(0xffffffffu, pre, off);
    if ((tid & 31) == 0) wsum[tid >> 5] = pre;
    __syncthreads();
    if (tid == 0) {
        int s = 0;
#pragma unroll
        for (int w = 0; w < 32; w++) s += wsum[w];
        s_off = s;
    }
    __syncthreads();
    int blockoff = s_off;

    if (i < n) {
        int r = sh[tid] - v + blockoff;
        g_rowptr[i] = r;
        g_cursor[i] = r;
    }
    if (i == 0) g_rowptr[n] = e_total;
}

// ---------- bf16 GEMM (R13 config: 4-stage cp.async ring) + scatter ---------
// Block 128x128; grid (2, Mtiles) for L2 A reuse. 8 warps (4x2), tile 32x64.

#define AS 24
#define BSTR 136
#define STAGES 4
#define A_TILE (128 * AS)
#define B_TILE (16 * BSTR)

__global__ __launch_bounds__(256, 2)
void k_gemm_scatter(int M, const int* __restrict__ esrc,
                    const int* __restrict__ edst, int E) {
    __shared__ __nv_bfloat16 Ah[STAGES * A_TILE];
    __shared__ __nv_bfloat16 Bh[STAGES * B_TILE];

    int tid = threadIdx.x;
    int bm = blockIdx.y * 128;   // M-tile
    int bn = blockIdx.x * 128;   // N-tile (grid.x = 2; pair co-resident)
    int wid = tid >> 5;
    int lane = tid & 31;
    int wm = (wid & 3) * 32;
    int wn = (wid >> 2) * 64;
    int qr = lane >> 2, qc = lane & 3;

    int arow = tid >> 1, ach = (tid & 1) * 8;
    int brow = tid >> 4, bch = (tid & 15) * 8;
    uint32_t adA = smem_u32(&Ah[arow * AS + ach]);
    uint32_t adB = smem_u32(&Bh[brow * BSTR + bch]);
    int ar = bm + arow;
    int aValid = (ar < M) ? 16 : 0;
    if (ar >= M) ar = M - 1;
    const __nv_bfloat16* aSrc = g_xb + (size_t)ar * 256 + ach;
    const __nv_bfloat16* bSrc = g_wb + (size_t)brow * 256 + bn + bch;

    int la = lane & 15, lb = lane >> 4;
    uint32_t adAh = smem_u32(Ah) + (uint32_t)(((wm + la) * AS + lb * 8) * 2);
    uint32_t adBh = smem_u32(Bh) + (uint32_t)((la * BSTR + wn + lb * 8) * 2);

    float d[2][8][4];
#pragma unroll
    for (int i = 0; i < 2; i++)
#pragma unroll
        for (int j = 0; j < 8; j++)
#pragma unroll
            for (int q = 0; q < 4; q++) d[i][j][q] = 0.0f;

    // prologue: stages 0..2
#pragma unroll
    for (int s = 0; s < STAGES - 1; s++) {
        cp_async16(adA + s * A_TILE * 2, aSrc + s * 16, aValid);
        cp_async16(adB + s * B_TILE * 2, bSrc + (size_t)(s * 16) * 256, 16);
        cp_commit();
    }

    for (int t = 0; t < 16; t++) {
        cp_wait<STAGES - 2>();
        __syncthreads();

        int nt = t + STAGES - 1;
        if (nt < 16) {
            int slot = nt & (STAGES - 1);
            cp_async16(adA + slot * A_TILE * 2, aSrc + nt * 16, aValid);
            cp_async16(adB + slot * B_TILE * 2, bSrc + (size_t)(nt * 16) * 256, 16);
        }
        cp_commit();

        int slot = t & (STAGES - 1);
        uint32_t aoff = (uint32_t)(slot * A_TILE * 2);
        uint32_t boff = (uint32_t)(slot * B_TILE * 2);
        uint32_t ah0[4], ah1[4];
        ldsm4(ah0, adAh + aoff);
        ldsm4(ah1, adAh + aoff + 16 * AS * 2);
#pragma unroll
        for (int q = 0; q < 4; q++) {
            uint32_t bh[4];
            ldsm4t(bh, adBh + boff + q * 32);
            mma_bf16(d[0][2 * q],     ah0, bh[0], bh[1]);
            mma_bf16(d[1][2 * q],     ah1, bh[0], bh[1]);
            mma_bf16(d[0][2 * q + 1], ah0, bh[2], bh[3]);
            mma_bf16(d[1][2 * q + 1], ah1, bh[2], bh[3]);
        }
    }

    // epilogue: * dis[row], convert to e4m3 pairs, 2B stores
#pragma unroll
    for (int ma = 0; ma < 2; ma++) {
        int r0 = bm + wm + 16 * ma + qr;
        int r1 = r0 + 8;
        float w0 = (r0 < M) ? g_dis[r0] : 0.0f;
        float w1 = (r1 < M) ? g_dis[r1] : 0.0f;
#pragma unroll
        for (int na = 0; na < 8; na++) {
            int c = bn + wn + 8 * na + 2 * qc;
            if (r0 < M) {
                uint16_t p = f2e4m3x2(d[ma][na][0] * w0, d[ma][na][1] * w0);
                *(uint16_t*)(&g_h8[(size_t)r0 * 256 + c]) = p;
            }
            if (r1 < M) {
                uint16_t p = f2e4m3x2(d[ma][na][2] * w1, d[ma][na][3] * w1);
                *(uint16_t*)(&g_h8[(size_t)r1 * 256 + c]) = p;
            }
        }
    }

    // ---- tail: scatter this block's slice of edges into CSR (+ coef) ----
    {
        int nblocks = gridDim.x * gridDim.y;
        int bid = blockIdx.y * gridDim.x + blockIdx.x;
        int per = (E + nblocks - 1) / nblocks;
        int e0 = bid * per;
        int e1 = min(e0 + per, E);
        for (int i = e0 + tid; i < e1; i += 256) {
            int s = esrc[i];
            int dd = edst[i];
            int p = atomicAdd(&g_cursor[dd], 1);
            g_col[p] = s;
            atomicAdd(&g_coef[s], g_dis[dd]);
        }
    }
}

// -------------------- fused aggregation + weighted reduce -------------------
// 8 rows / block (one warp per row); lane l owns cols l*8..l*8+7 (uint2 of
// 8 e4m3). Next batch's column indices prefetched during the shfl loop.

__device__ __forceinline__ __half2 e8_to_h2(uint16_t w) {
    uint32_t r;
    asm("cvt.rn.f16x2.e4m3x2 %0, %1;" : "=r"(r) : "h"(w));
    return *(__half2*)&r;
}

__global__ __launch_bounds__(256)
void k_agg_fused(const float* __restrict__ bias, int n) {
    __shared__ float sh[8][256];

    int lane = threadIdx.x & 31;
    int w = threadIdx.x >> 5;
    int i = blockIdx.x * 8 + w;

    const uint2* __restrict__ hp = (const uint2*)g_h8;
    float res[8];
#pragma unroll
    for (int q = 0; q < 8; q++) res[q] = 0.0f;

    if (i < n) {
        int s = g_rowptr[i];
        int t = g_rowptr[i + 1];
        float di = g_dis[i];
        float ci = di * (g_coef[i] + di);

        __half2 acc[4];
        {
            uint2 sv = hp[(size_t)i * 32 + lane];
            acc[0] = e8_to_h2((uint16_t)(sv.x & 0xffffu));
            acc[1] = e8_to_h2((uint16_t)(sv.x >> 16));
            acc[2] = e8_to_h2((uint16_t)(sv.y & 0xffffu));
            acc[3] = e8_to_h2((uint16_t)(sv.y >> 16));
        }

        int jv = (s + lane < t) ? g_col[s + lane] : 0;
        for (int base = s; base < t; base += 32) {
            int m = min(32, t - base);
            int nb = base + 32;
            int jvn = (nb + lane < t) ? g_col[nb + lane] : 0;  // prefetch
#pragma unroll 8
            for (int k = 0; k < m; k++) {
                int j = __shfl_sync(0xffffffffu, jv, k);
                uint2 v = hp[(size_t)j * 32 + lane];
                acc[0] = __hadd2(acc[0], e8_to_h2((uint16_t)(v.x & 0xffffu)));
                acc[1] = __hadd2(acc[1], e8_to_h2((uint16_t)(v.x >> 16)));
                acc[2] = __hadd2(acc[2], e8_to_h2((uint16_t)(v.y & 0xffffu)));
                acc[3] = __hadd2(acc[3], e8_to_h2((uint16_t)(v.y >> 16)));
            }
            jv = jvn;
        }

        float4 b0 = *(const float4*)(bias + lane * 8);
        float4 b1 = *(const float4*)(bias + lane * 8 + 4);
        float2 f0 = __half22float2(acc[0]);
        float2 f1 = __half22float2(acc[1]);
        float2 f2 = __half22float2(acc[2]);
        float2 f3 = __half22float2(acc[3]);
        res[0] = fmaxf(f0.x * di + b0.x, 0.f) * ci;
        res[1] = fmaxf(f0.y * di + b0.y, 0.f) * ci;
        res[2] = fmaxf(f1.x * di + b0.z, 0.f) * ci;
        res[3] = fmaxf(f1.y * di + b0.w, 0.f) * ci;
        res[4] = fmaxf(f2.x * di + b1.x, 0.f) * ci;
        res[5] = fmaxf(f2.y * di + b1.y, 0.f) * ci;
        res[6] = fmaxf(f3.x * di + b1.z, 0.f) * ci;
        res[7] = fmaxf(f3.y * di + b1.w, 0.f) * ci;
    }

#pragma unroll
    for (int q = 0; q < 8; q++) sh[w][lane * 8 + q] = res[q];
    __syncthreads();

    int c = threadIdx.x;
    float ssum = 0.0f;
#pragma unroll
    for (int q = 0; q < 8; q++) ssum += sh[q][c];
    g_part[(size_t)blockIdx.x * 256 + c] = ssum;
}

// ------------------------------- reductions --------------------------------

__global__ void k_reduce_stage1(int nb) {
    int c = threadIdx.x;
    int rows_per = (nb + 255) / 256;
    int r0 = blockIdx.x * rows_per;
    int r1 = min(r0 + rows_per, nb);
    float s = 0.0f;
    for (int r = r0; r < r1; r++) s += g_part[(size_t)r * 256 + c];
    g_part2[blockIdx.x * 256 + c] = s;
}

__global__ void k_final(const float* __restrict__ W2, const float* __restrict__ b2,
                        float* __restrict__ out, int n) {
    __shared__ float z[256];
    int c = threadIdx.x;
    float s = 0.0f;
    for (int b = 0; b < 256; b++) s += g_part2[b * 256 + c];
    z[c] = s / (float)n;
    __syncthreads();

    float o = b2[c];
#pragma unroll 8
    for (int k = 0; k < 256; k++) o += z[k] * W2[k * 256 + c];
    out[c] = o;
}

// -------------------------------- launch -----------------------------------

extern "C" void kernel_launch(void* const* d_in, const int* in_sizes, int n_in,
                              void* d_out, int out_size) {
    const float* x  = (const float*)d_in[0];
    const float* W1 = (const float*)d_in[1];
    const float* b1 = (const float*)d_in[2];
    const float* W2 = (const float*)d_in[3];
    const float* b2 = (const float*)d_in[4];
    const int*   ei = (const int*)d_in[5];

    int n = in_sizes[0] / DIM;
    int e = in_sizes[5] / 2;
    const int* src = ei;
    const int* dst = ei + e;
    float* out = (float*)d_out;

    int nb1024 = (n + 1023) / 1024;
    int agg_blocks = (n + 7) / 8;

    // zero deg/coef/publish-words via memset nodes (not kernel launches)
    void* p_deg;
    void* p_coef;
    void* p_bpub;
    cudaGetSymbolAddress(&p_deg, g_deg);
    cudaGetSymbolAddress(&p_coef, g_coef);
    cudaGetSymbolAddress(&p_bpub, g_bpub);
    cudaMemsetAsync(p_deg, 0, (size_t)n * sizeof(int));
    cudaMemsetAsync(p_coef, 0, (size_t)n * sizeof(float));
    cudaMemsetAsync(p_bpub, 0, (size_t)nb1024 * sizeof(unsigned long long));

    // --- degree count + bf16 conversion of x, W1 ---
    k_count_convert<<<(e + 255) / 256, 256>>>(dst, e, x, W1, n);

    // --- fused scan: dis + rowptr + cursor (single kernel) ---
    k_scan_fused<<<nb1024, 1024>>>(n, e);

    // --- layer-1 GEMM (bf16, R13 config) + fused edge scatter tail ---
    dim3 gemm_grid(2, (n + 127) / 128);
    k_gemm_scatter<<<gemm_grid, 256>>>(n, src, dst, e);

    // --- fused aggregate + relu + weighted reduce (layer 2 collapsed) ---
    k_agg_fused<<<agg_blocks, 256>>>(b1, n);

    // --- reduce partials, matvec with W2, bias, mean ---
    k_reduce_stage1<<<256, 256>>>(agg_blocks);
    k_final<<<1, 256>>>(W2, b2, out, n);
}